// round 2
// baseline (speedup 1.0000x reference)
#include <cuda_runtime.h>
#include <cuda_bf16.h>
#include <math.h>

// ---------------------------------------------------------------------------
// GNN-VAE: x_recon = GCN(relu(fc(fc(GCN...)))) pipeline
// Dims: N=50000, E=800000, F: 256 -> 64 -> 32 -> 64 -> 256, pred dim 3
// Output layout: [x_recon (N*256) | z (N*32) | pred (N*3)]
// ---------------------------------------------------------------------------

#define MAXN 50048
#define MAXE 800000

// Scratch (device globals; no allocation allowed)
__device__ float g_h1[(size_t)MAXN * 64];    // x @ W_enc_gnn
__device__ float g_agg1[(size_t)MAXN * 64];  // relu(agg(h1) + b)  (encoder GCN out)
__device__ float g_hd[(size_t)MAXN * 64];    // relu(z @ W_dec_fc + b)
__device__ float g_hd2[(size_t)MAXN * 256];  // hd @ W_dec_gnn
__device__ int   g_cnt[MAXN];                // in-degree (real edges)
__device__ int   g_offs[MAXN];               // CSR offsets (exclusive scan)
__device__ int   g_cursor[MAXN];             // scatter cursors
__device__ int   g_ssrc[MAXE];               // src sorted by dst
__device__ float g_dinv[MAXN];               // rsqrt(deg+1)

// ---------------------------------------------------------------------------
// Graph preprocessing
// ---------------------------------------------------------------------------
__global__ void zero_cnt_kernel(int N) {
    int i = blockIdx.x * blockDim.x + threadIdx.x;
    if (i < N) g_cnt[i] = 0;
}

__global__ void count_kernel(const int* __restrict__ dst, int E) {
    int e = blockIdx.x * blockDim.x + threadIdx.x;
    if (e < E) atomicAdd(&g_cnt[dst[e]], 1);
}

// Single-block exclusive scan over counts; also fills cursor and dinv.
__global__ void scan_kernel(int N) {
    __shared__ int sh[1024];
    int t = threadIdx.x;
    int per = (N + 1023) >> 10;
    int beg = t * per;
    int end = beg + per; if (end > N) end = N;
    int s = 0;
    for (int i = beg; i < end; i++) s += g_cnt[i];
    sh[t] = s;
    __syncthreads();
    // Hillis-Steele inclusive scan
    for (int off = 1; off < 1024; off <<= 1) {
        int v = (t >= off) ? sh[t - off] : 0;
        __syncthreads();
        sh[t] += v;
        __syncthreads();
    }
    int run = (t > 0) ? sh[t - 1] : 0;
    for (int i = beg; i < end; i++) {
        g_offs[i] = run;
        g_cursor[i] = run;
        int c = g_cnt[i];
        run += c;
        g_dinv[i] = rsqrtf((float)(c + 1));  // +1 for self loop; always > 0
    }
}

__global__ void scatter_kernel(const int* __restrict__ src,
                               const int* __restrict__ dst, int E) {
    int e = blockIdx.x * blockDim.x + threadIdx.x;
    if (e < E) {
        int d = dst[e];
        int p = atomicAdd(&g_cursor[d], 1);
        g_ssrc[p] = src[e];
    }
}

// ---------------------------------------------------------------------------
// SGEMM: C[M,N] = A[M,K] @ B[K,N], row-major. BM=128, BN=64, BK=32,
// 256 threads, 8x4 microtile per thread.
// ---------------------------------------------------------------------------
__global__ __launch_bounds__(256) void sgemm_kernel(
    const float* __restrict__ A, const float* __restrict__ B,
    float* __restrict__ C, int M, int N, int K) {
    const int BM = 128, BN = 64, BK = 32;
    __shared__ float As[BK][BM + 1];
    __shared__ float Bs[BK][BN];
    int t = threadIdx.x;
    int tx = t & 15;   // col group 0..15  (cols tx*4 .. tx*4+3)
    int ty = t >> 4;   // row group 0..15  (rows ty*8 .. ty*8+7)
    int rowBase = blockIdx.y * BM;
    int colBase = blockIdx.x * BN;

    float acc[8][4];
#pragma unroll
    for (int i = 0; i < 8; i++)
#pragma unroll
        for (int j = 0; j < 4; j++) acc[i][j] = 0.f;

    for (int k0 = 0; k0 < K; k0 += BK) {
        // A tile: 128x32 = 4096 elems, 16 per thread, coalesced along K
#pragma unroll
        for (int l = 0; l < 16; l++) {
            int idx = t + l * 256;
            int r = idx >> 5;
            int kk = idx & 31;
            int gr = rowBase + r;
            As[kk][r] = (gr < M) ? A[(size_t)gr * K + k0 + kk] : 0.f;
        }
        // B tile: 32x64 = 2048 elems, 8 per thread, coalesced along N
#pragma unroll
        for (int l = 0; l < 8; l++) {
            int idx = t + l * 256;
            int kk = idx >> 6;
            int c = idx & 63;
            Bs[kk][c] = B[(size_t)(k0 + kk) * N + colBase + c];
        }
        __syncthreads();
#pragma unroll
        for (int k = 0; k < BK; k++) {
            float a[8], b[4];
#pragma unroll
            for (int i = 0; i < 8; i++) a[i] = As[k][ty * 8 + i];
#pragma unroll
            for (int j = 0; j < 4; j++) b[j] = Bs[k][tx * 4 + j];
#pragma unroll
            for (int i = 0; i < 8; i++)
#pragma unroll
                for (int j = 0; j < 4; j++) acc[i][j] = fmaf(a[i], b[j], acc[i][j]);
        }
        __syncthreads();
    }
#pragma unroll
    for (int i = 0; i < 8; i++) {
        int gr = rowBase + ty * 8 + i;
        if (gr < M) {
#pragma unroll
            for (int j = 0; j < 4; j++)
                C[(size_t)gr * N + colBase + tx * 4 + j] = acc[i][j];
        }
    }
}

// ---------------------------------------------------------------------------
// Aggregation F=64: agg1[n] = relu( dinv[n]*(sum dinv[s]*h1[s] + dinv[n]*h1[n]) + b )
// 4 nodes per 256-thread block, 64 threads per node.
// ---------------------------------------------------------------------------
__global__ __launch_bounds__(256) void agg64_kernel(const float* __restrict__ bias, int N) {
    int node = blockIdx.x * 4 + (threadIdx.x >> 6);
    int f = threadIdx.x & 63;
    if (node >= N) return;
    int beg = g_offs[node];
    int cnt = g_cnt[node];
    float acc = 0.f;
    int e = 0;
    for (; e + 4 <= cnt; e += 4) {
        int s0 = g_ssrc[beg + e + 0];
        int s1 = g_ssrc[beg + e + 1];
        int s2 = g_ssrc[beg + e + 2];
        int s3 = g_ssrc[beg + e + 3];
        float w0 = g_dinv[s0], w1 = g_dinv[s1], w2 = g_dinv[s2], w3 = g_dinv[s3];
        float v0 = g_h1[(size_t)s0 * 64 + f];
        float v1 = g_h1[(size_t)s1 * 64 + f];
        float v2 = g_h1[(size_t)s2 * 64 + f];
        float v3 = g_h1[(size_t)s3 * 64 + f];
        acc = fmaf(w0, v0, acc);
        acc = fmaf(w1, v1, acc);
        acc = fmaf(w2, v2, acc);
        acc = fmaf(w3, v3, acc);
    }
    for (; e < cnt; e++) {
        int s = g_ssrc[beg + e];
        acc = fmaf(g_dinv[s], g_h1[(size_t)s * 64 + f], acc);
    }
    float dn = g_dinv[node];
    float o = dn * (acc + dn * g_h1[(size_t)node * 64 + f]) + bias[f];
    g_agg1[(size_t)node * 64 + f] = fmaxf(o, 0.f);
}

// ---------------------------------------------------------------------------
// Aggregation F=256: x_recon[n] = dinv[n]*(sum dinv[s]*hd2[s] + dinv[n]*hd2[n]) + b
// 1 node per 256-thread block.
// ---------------------------------------------------------------------------
__global__ __launch_bounds__(256) void agg256_kernel(const float* __restrict__ bias,
                                                     float* __restrict__ out, int N) {
    int node = blockIdx.x;
    if (node >= N) return;
    int f = threadIdx.x;
    int beg = g_offs[node];
    int cnt = g_cnt[node];
    float acc = 0.f;
    int e = 0;
    for (; e + 4 <= cnt; e += 4) {
        int s0 = g_ssrc[beg + e + 0];
        int s1 = g_ssrc[beg + e + 1];
        int s2 = g_ssrc[beg + e + 2];
        int s3 = g_ssrc[beg + e + 3];
        float w0 = g_dinv[s0], w1 = g_dinv[s1], w2 = g_dinv[s2], w3 = g_dinv[s3];
        float v0 = g_hd2[(size_t)s0 * 256 + f];
        float v1 = g_hd2[(size_t)s1 * 256 + f];
        float v2 = g_hd2[(size_t)s2 * 256 + f];
        float v3 = g_hd2[(size_t)s3 * 256 + f];
        acc = fmaf(w0, v0, acc);
        acc = fmaf(w1, v1, acc);
        acc = fmaf(w2, v2, acc);
        acc = fmaf(w3, v3, acc);
    }
    for (; e < cnt; e++) {
        int s = g_ssrc[beg + e];
        acc = fmaf(g_dinv[s], g_hd2[(size_t)s * 256 + f], acc);
    }
    float dn = g_dinv[node];
    out[(size_t)node * 256 + f] =
        dn * (acc + dn * g_hd2[(size_t)node * 256 + f]) + bias[f];
}

// ---------------------------------------------------------------------------
// Fused latent chain: z = agg1 @ Wz + bz ; pred = z @ Wp + bp ;
// hd = relu(z @ Wd + bd). 8 rows per 256-thread block (1 warp per row).
// ---------------------------------------------------------------------------
__global__ __launch_bounds__(256) void latent_kernel(
    const float* __restrict__ Wz, const float* __restrict__ bz,
    const float* __restrict__ Wd, const float* __restrict__ bd,
    const float* __restrict__ Wp, const float* __restrict__ bp,
    float* __restrict__ zout, float* __restrict__ pout, int N) {
    __shared__ float sWz[64 * 32];
    __shared__ float sWd[32 * 64];
    __shared__ float sWp[32 * 3];
    __shared__ float sz[8][33];
    int t = threadIdx.x;
    for (int i = t; i < 64 * 32; i += 256) sWz[i] = Wz[i];
    for (int i = t; i < 32 * 64; i += 256) sWd[i] = Wd[i];
    if (t < 96) sWp[t] = Wp[t];
    __syncthreads();

    int r = t >> 5;
    int lane = t & 31;
    int row = blockIdx.x * 8 + r;

    float zv = 0.f;
    if (row < N) {
        zv = bz[lane];
        const float* hrow = &g_agg1[(size_t)row * 64];
#pragma unroll
        for (int k = 0; k < 64; k++) zv = fmaf(hrow[k], sWz[k * 32 + lane], zv);
        zout[(size_t)row * 32 + lane] = zv;
    }
    sz[r][lane] = zv;

    // pred = z @ Wp + bp, via warp butterfly reduce
    float p0 = zv * sWp[lane * 3 + 0];
    float p1 = zv * sWp[lane * 3 + 1];
    float p2 = zv * sWp[lane * 3 + 2];
#pragma unroll
    for (int off = 16; off; off >>= 1) {
        p0 += __shfl_xor_sync(0xffffffffu, p0, off);
        p1 += __shfl_xor_sync(0xffffffffu, p1, off);
        p2 += __shfl_xor_sync(0xffffffffu, p2, off);
    }
    if (row < N && lane == 0) {
        pout[(size_t)row * 3 + 0] = p0 + bp[0];
        pout[(size_t)row * 3 + 1] = p1 + bp[1];
        pout[(size_t)row * 3 + 2] = p2 + bp[2];
    }
    __syncthreads();

    // hd = relu(z @ Wd + bd), each lane computes cols lane, lane+32
    if (row < N) {
        float a0 = bd[lane], a1 = bd[lane + 32];
#pragma unroll
        for (int c = 0; c < 32; c++) {
            float zc = sz[r][c];
            a0 = fmaf(zc, sWd[c * 64 + lane], a0);
            a1 = fmaf(zc, sWd[c * 64 + lane + 32], a1);
        }
        g_hd[(size_t)row * 64 + lane] = fmaxf(a0, 0.f);
        g_hd[(size_t)row * 64 + lane + 32] = fmaxf(a1, 0.f);
    }
}

// ---------------------------------------------------------------------------
// Launch
// ---------------------------------------------------------------------------
extern "C" void kernel_launch(void* const* d_in, const int* in_sizes, int n_in,
                              void* d_out, int out_size) {
    const float* x         = (const float*)d_in[0];
    const int*   ei        = (const int*)d_in[1];
    // d_in[2] = edge_attr (unused by reference)
    const float* W_enc_gnn = (const float*)d_in[3];
    const float* b_enc_gnn = (const float*)d_in[4];
    const float* W_enc_fc  = (const float*)d_in[5];
    const float* b_enc_fc  = (const float*)d_in[6];
    const float* W_dec_fc  = (const float*)d_in[7];
    const float* b_dec_fc  = (const float*)d_in[8];
    const float* W_dec_gnn = (const float*)d_in[9];
    const float* b_dec_gnn = (const float*)d_in[10];
    const float* W_cond    = (const float*)d_in[11];
    const float* b_cond    = (const float*)d_in[12];

    int N = in_sizes[0] / 256;
    int E = in_sizes[1] / 2;
    const int* src = ei;
    const int* dst = ei + E;

    float* out  = (float*)d_out;
    float* xr   = out;                        // [N,256]
    float* zout = out + (size_t)N * 256;      // [N,32]
    float* pout = out + (size_t)N * 288;      // [N,3]

    float *p_h1, *p_hd, *p_hd2;
    cudaGetSymbolAddress((void**)&p_h1, g_h1);
    cudaGetSymbolAddress((void**)&p_hd, g_hd);
    cudaGetSymbolAddress((void**)&p_hd2, g_hd2);

    // 1. graph prep (CSR by dst + dinv)
    zero_cnt_kernel<<<(N + 255) / 256, 256>>>(N);
    count_kernel<<<(E + 255) / 256, 256>>>(dst, E);
    scan_kernel<<<1, 1024>>>(N);
    scatter_kernel<<<(E + 255) / 256, 256>>>(src, dst, E);

    // 2. encoder GCN: h1 = x @ W_enc_gnn ; agg1 = relu(agg(h1) + b)
    sgemm_kernel<<<dim3(1, (N + 127) / 128), 256>>>(x, W_enc_gnn, p_h1, N, 64, 256);
    agg64_kernel<<<(N + 3) / 4, 256>>>(b_enc_gnn, N);

    // 3. latent chain: z, pred, hd
    latent_kernel<<<(N + 7) / 8, 256>>>(W_enc_fc, b_enc_fc, W_dec_fc, b_dec_fc,
                                        W_cond, b_cond, zout, pout, N);

    // 4. decoder GCN: hd2 = hd @ W_dec_gnn ; x_recon = agg(hd2) + b
    sgemm_kernel<<<dim3(4, (N + 127) / 128), 256>>>(p_hd, W_dec_gnn, p_hd2, N, 256, 64);
    agg256_kernel<<<N, 256>>>(b_dec_gnn, xr, N);
}

// round 5
// speedup vs baseline: 1.3594x; 1.3594x over previous
#include <cuda_runtime.h>
#include <cuda_bf16.h>
#include <math.h>

// ---------------------------------------------------------------------------
// GNN-VAE. Dims: N=50000, E=800000, F: 256 -> 64 -> 32 -> 64 -> 256, pred 3.
// Output layout: [x_recon (N*256) | z (N*32) | pred (N*3)]
//
// Decoder reordered using linearity of GCN propagation:
//   x_recon = (D^-1/2 A_hat D^-1/2 hd) @ W_dec_gnn + b
// so ALL edge gathers happen in 64-dim feature space.
// ---------------------------------------------------------------------------

#define MAXN 50048
#define MAXE 800000

__device__ float g_h1[(size_t)MAXN * 64];    // x @ W_enc_gnn ; later reused for agg(hd)
__device__ float g_agg1[(size_t)MAXN * 64];  // relu(agg(h1) + b)  (encoder GCN out)
__device__ float g_hd[(size_t)MAXN * 64];    // relu(z @ W_dec_fc + b)
__device__ float g_aggd[(size_t)MAXN * 64];  // agg(hd) (pre-GEMM decoder aggregate)
__device__ int   g_cnt[MAXN];
__device__ int   g_offs[MAXN];
__device__ int   g_cursor[MAXN];
__device__ int   g_ssrc[MAXE];
__device__ float g_dinv[MAXN];

// ---------------------------------------------------------------------------
// Graph preprocessing
// ---------------------------------------------------------------------------
__global__ void count_kernel(const int* __restrict__ dst, int E) {
    int e = blockIdx.x * blockDim.x + threadIdx.x;
    if (e < E) atomicAdd(&g_cnt[dst[e]], 1);
}

__global__ void scan_kernel(int N) {
    __shared__ int sh[1024];
    int t = threadIdx.x;
    int per = (N + 1023) >> 10;
    int beg = t * per;
    int end = beg + per; if (end > N) end = N;
    int s = 0;
    for (int i = beg; i < end; i++) s += g_cnt[i];
    sh[t] = s;
    __syncthreads();
    for (int off = 1; off < 1024; off <<= 1) {
        int v = (t >= off) ? sh[t - off] : 0;
        __syncthreads();
        sh[t] += v;
        __syncthreads();
    }
    int run = (t > 0) ? sh[t - 1] : 0;
    for (int i = beg; i < end; i++) {
        g_offs[i] = run;
        g_cursor[i] = run;
        int c = g_cnt[i];
        run += c;
        g_dinv[i] = rsqrtf((float)(c + 1));  // +1 for self loop
    }
}

__global__ void scatter_kernel(const int* __restrict__ src,
                               const int* __restrict__ dst, int E) {
    int e = blockIdx.x * blockDim.x + threadIdx.x;
    if (e < E) {
        int d = dst[e];
        int p = atomicAdd(&g_cursor[d], 1);
        g_ssrc[p] = src[e];
    }
}

// ---------------------------------------------------------------------------
// SGEMM: C[M,N] = A[M,K] @ B[K,N] (+ bias). BM=128, BN=64, BK=32,
// 256 threads, 8x4 microtile.
// ---------------------------------------------------------------------------
__global__ __launch_bounds__(256) void sgemm_kernel(
    const float* __restrict__ A, const float* __restrict__ B,
    float* __restrict__ C, const float* __restrict__ bias,
    int M, int N, int K) {
    const int BM = 128, BN = 64, BK = 32;
    __shared__ float As[BK][BM + 1];
    __shared__ float Bs[BK][BN];
    int t = threadIdx.x;
    int tx = t & 15;
    int ty = t >> 4;
    int rowBase = blockIdx.y * BM;
    int colBase = blockIdx.x * BN;

    float acc[8][4];
#pragma unroll
    for (int i = 0; i < 8; i++)
#pragma unroll
        for (int j = 0; j < 4; j++) acc[i][j] = 0.f;

    for (int k0 = 0; k0 < K; k0 += BK) {
#pragma unroll
        for (int l = 0; l < 16; l++) {
            int idx = t + l * 256;
            int r = idx >> 5;
            int kk = idx & 31;
            int gr = rowBase + r;
            As[kk][r] = (gr < M) ? A[(size_t)gr * K + k0 + kk] : 0.f;
        }
#pragma unroll
        for (int l = 0; l < 8; l++) {
            int idx = t + l * 256;
            int kk = idx >> 6;
            int c = idx & 63;
            Bs[kk][c] = B[(size_t)(k0 + kk) * N + colBase + c];
        }
        __syncthreads();
#pragma unroll
        for (int k = 0; k < BK; k++) {
            float a[8], b[4];
#pragma unroll
            for (int i = 0; i < 8; i++) a[i] = As[k][ty * 8 + i];
#pragma unroll
            for (int j = 0; j < 4; j++) b[j] = Bs[k][tx * 4 + j];
#pragma unroll
            for (int i = 0; i < 8; i++)
#pragma unroll
                for (int j = 0; j < 4; j++) acc[i][j] = fmaf(a[i], b[j], acc[i][j]);
        }
        __syncthreads();
    }
    float bv[4] = {0.f, 0.f, 0.f, 0.f};
    if (bias) {
#pragma unroll
        for (int j = 0; j < 4; j++) bv[j] = bias[colBase + tx * 4 + j];
    }
#pragma unroll
    for (int i = 0; i < 8; i++) {
        int gr = rowBase + ty * 8 + i;
        if (gr < M) {
#pragma unroll
            for (int j = 0; j < 4; j++)
                C[(size_t)gr * N + colBase + tx * 4 + j] = acc[i][j] + bv[j];
        }
    }
}

// ---------------------------------------------------------------------------
// Vectorized 64-wide aggregation: 16 lanes/node (float4 each), 16 nodes/block.
// out[n] = post( dinv[n]*(sum_in dinv[s]*in[s] + dinv[n]*in[n]) [+ bias] )
// RELU template flag: encoder uses bias+relu, decoder uses neither.
// ---------------------------------------------------------------------------
template <bool RELU, bool BIAS>
__global__ __launch_bounds__(256) void agg64v_kernel(
    const float* __restrict__ in, float* __restrict__ out,
    const float* __restrict__ bias, int N) {
    int node = blockIdx.x * 16 + (threadIdx.x >> 4);
    int q = threadIdx.x & 15;
    if (node >= N) return;
    const float4* F = (const float4*)in;
    int beg = g_offs[node];
    int cnt = g_cnt[node];
    float4 acc = make_float4(0.f, 0.f, 0.f, 0.f);
    int e = 0;
    for (; e + 4 <= cnt; e += 4) {
        int s0 = g_ssrc[beg + e + 0];
        int s1 = g_ssrc[beg + e + 1];
        int s2 = g_ssrc[beg + e + 2];
        int s3 = g_ssrc[beg + e + 3];
        float w0 = g_dinv[s0], w1 = g_dinv[s1], w2 = g_dinv[s2], w3 = g_dinv[s3];
        float4 v0 = F[(size_t)s0 * 16 + q];
        float4 v1 = F[(size_t)s1 * 16 + q];
        float4 v2 = F[(size_t)s2 * 16 + q];
        float4 v3 = F[(size_t)s3 * 16 + q];
        acc.x = fmaf(w0, v0.x, acc.x); acc.y = fmaf(w0, v0.y, acc.y);
        acc.z = fmaf(w0, v0.z, acc.z); acc.w = fmaf(w0, v0.w, acc.w);
        acc.x = fmaf(w1, v1.x, acc.x); acc.y = fmaf(w1, v1.y, acc.y);
        acc.z = fmaf(w1, v1.z, acc.z); acc.w = fmaf(w1, v1.w, acc.w);
        acc.x = fmaf(w2, v2.x, acc.x); acc.y = fmaf(w2, v2.y, acc.y);
        acc.z = fmaf(w2, v2.z, acc.z); acc.w = fmaf(w2, v2.w, acc.w);
        acc.x = fmaf(w3, v3.x, acc.x); acc.y = fmaf(w3, v3.y, acc.y);
        acc.z = fmaf(w3, v3.z, acc.z); acc.w = fmaf(w3, v3.w, acc.w);
    }
    for (; e < cnt; e++) {
        int s = g_ssrc[beg + e];
        float w = g_dinv[s];
        float4 v = F[(size_t)s * 16 + q];
        acc.x = fmaf(w, v.x, acc.x); acc.y = fmaf(w, v.y, acc.y);
        acc.z = fmaf(w, v.z, acc.z); acc.w = fmaf(w, v.w, acc.w);
    }
    float dn = g_dinv[node];
    float4 sv = F[(size_t)node * 16 + q];
    float4 o;
    o.x = dn * fmaf(dn, sv.x, acc.x);
    o.y = dn * fmaf(dn, sv.y, acc.y);
    o.z = dn * fmaf(dn, sv.z, acc.z);
    o.w = dn * fmaf(dn, sv.w, acc.w);
    if (BIAS) {
        float4 b = ((const float4*)bias)[q];
        o.x += b.x; o.y += b.y; o.z += b.z; o.w += b.w;
    }
    if (RELU) {
        o.x = fmaxf(o.x, 0.f); o.y = fmaxf(o.y, 0.f);
        o.z = fmaxf(o.z, 0.f); o.w = fmaxf(o.w, 0.f);
    }
    ((float4*)out)[(size_t)node * 16 + q] = o;
}

// ---------------------------------------------------------------------------
// Fused latent chain: z = agg1 @ Wz + bz ; pred = z @ Wp + bp ;
// hd = relu(z @ Wd + bd). 8 rows per block (1 warp per row).
// ---------------------------------------------------------------------------
__global__ __launch_bounds__(256) void latent_kernel(
    const float* __restrict__ Wz, const float* __restrict__ bz,
    const float* __restrict__ Wd, const float* __restrict__ bd,
    const float* __restrict__ Wp, const float* __restrict__ bp,
    float* __restrict__ zout, float* __restrict__ pout, int N) {
    __shared__ float sWz[64 * 32];
    __shared__ float sWd[32 * 64];
    __shared__ float sWp[32 * 3];
    __shared__ float sz[8][33];
    int t = threadIdx.x;
    for (int i = t; i < 64 * 32; i += 256) sWz[i] = Wz[i];
    for (int i = t; i < 32 * 64; i += 256) sWd[i] = Wd[i];
    if (t < 96) sWp[t] = Wp[t];
    __syncthreads();

    int r = t >> 5;
    int lane = t & 31;
    int row = blockIdx.x * 8 + r;

    float zv = 0.f;
    if (row < N) {
        zv = bz[lane];
        const float* hrow = &g_agg1[(size_t)row * 64];
#pragma unroll
        for (int k = 0; k < 64; k++) zv = fmaf(hrow[k], sWz[k * 32 + lane], zv);
        zout[(size_t)row * 32 + lane] = zv;
    }
    sz[r][lane] = zv;

    float p0 = zv * sWp[lane * 3 + 0];
    float p1 = zv * sWp[lane * 3 + 1];
    float p2 = zv * sWp[lane * 3 + 2];
#pragma unroll
    for (int off = 16; off; off >>= 1) {
        p0 += __shfl_xor_sync(0xffffffffu, p0, off);
        p1 += __shfl_xor_sync(0xffffffffu, p1, off);
        p2 += __shfl_xor_sync(0xffffffffu, p2, off);
    }
    if (row < N && lane == 0) {
        pout[(size_t)row * 3 + 0] = p0 + bp[0];
        pout[(size_t)row * 3 + 1] = p1 + bp[1];
        pout[(size_t)row * 3 + 2] = p2 + bp[2];
    }
    __syncthreads();

    if (row < N) {
        float a0 = bd[lane], a1 = bd[lane + 32];
#pragma unroll
        for (int c = 0; c < 32; c++) {
            float zc = sz[r][c];
            a0 = fmaf(zc, sWd[c * 64 + lane], a0);
            a1 = fmaf(zc, sWd[c * 64 + lane + 32], a1);
        }
        g_hd[(size_t)row * 64 + lane] = fmaxf(a0, 0.f);
        g_hd[(size_t)row * 64 + lane + 32] = fmaxf(a1, 0.f);
    }
}

// ---------------------------------------------------------------------------
// Launch
// ---------------------------------------------------------------------------
extern "C" void kernel_launch(void* const* d_in, const int* in_sizes, int n_in,
                              void* d_out, int out_size) {
    const float* x         = (const float*)d_in[0];
    const int*   ei        = (const int*)d_in[1];
    const float* W_enc_gnn = (const float*)d_in[3];
    const float* b_enc_gnn = (const float*)d_in[4];
    const float* W_enc_fc  = (const float*)d_in[5];
    const float* b_enc_fc  = (const float*)d_in[6];
    const float* W_dec_fc  = (const float*)d_in[7];
    const float* b_dec_fc  = (const float*)d_in[8];
    const float* W_dec_gnn = (const float*)d_in[9];
    const float* b_dec_gnn = (const float*)d_in[10];
    const float* W_cond    = (const float*)d_in[11];
    const float* b_cond    = (const float*)d_in[12];

    int N = in_sizes[0] / 256;
    int E = in_sizes[1] / 2;
    const int* src = ei;
    const int* dst = ei + E;

    float* out  = (float*)d_out;
    float* xr   = out;                        // [N,256]
    float* zout = out + (size_t)N * 256;      // [N,32]
    float* pout = out + (size_t)N * 288;      // [N,3]

    float *p_h1, *p_agg1, *p_hd, *p_aggd;
    int* p_cnt;
    cudaGetSymbolAddress((void**)&p_h1, g_h1);
    cudaGetSymbolAddress((void**)&p_agg1, g_agg1);
    cudaGetSymbolAddress((void**)&p_hd, g_hd);
    cudaGetSymbolAddress((void**)&p_aggd, g_aggd);
    cudaGetSymbolAddress((void**)&p_cnt, g_cnt);

    // 1. graph prep (CSR by dst + dinv)
    cudaMemsetAsync(p_cnt, 0, (size_t)N * sizeof(int));
    count_kernel<<<(E + 255) / 256, 256>>>(dst, E);
    scan_kernel<<<1, 1024>>>(N);
    scatter_kernel<<<(E + 255) / 256, 256>>>(src, dst, E);

    // 2. encoder GCN: h1 = x @ W_enc_gnn ; agg1 = relu(agg(h1) + b)
    sgemm_kernel<<<dim3(1, (N + 127) / 128), 256>>>(x, W_enc_gnn, p_h1, nullptr,
                                                    N, 64, 256);
    agg64v_kernel<true, true><<<(N + 15) / 16, 256>>>(p_h1, p_agg1, b_enc_gnn, N);

    // 3. latent chain: z, pred, hd
    latent_kernel<<<(N + 7) / 8, 256>>>(W_enc_fc, b_enc_fc, W_dec_fc, b_dec_fc,
                                        W_cond, b_cond, zout, pout, N);

    // 4. decoder GCN reordered: aggd = agg(hd) (64-wide) ;
    //    x_recon = aggd @ W_dec_gnn + b  (written straight to output)
    agg64v_kernel<false, false><<<(N + 15) / 16, 256>>>(p_hd, p_aggd, nullptr, N);
    sgemm_kernel<<<dim3(4, (N + 127) / 128), 256>>>(p_aggd, W_dec_gnn, xr,
                                                    b_dec_gnn, N, 256, 64);
}

// round 6
// speedup vs baseline: 1.3905x; 1.0229x over previous
#include <cuda_runtime.h>
#include <cuda_bf16.h>
#include <math.h>

// ---------------------------------------------------------------------------
// GNN-VAE. Dims: N=50000, E=800000, F: 256 -> 64 -> 32 -> 64 -> 256, pred 3.
// Output layout: [x_recon (N*256) | z (N*32) | pred (N*3)]
// Decoder reordered via GCN linearity: all edge gathers in 64-dim space.
// GEMMs use packed fma.rn.f32x2 (FFMA2): 2 fp32 FMA per issued instruction,
// bitwise identical to scalar fmaf.
// ---------------------------------------------------------------------------

#define MAXN 50048
#define MAXE 800000

typedef unsigned long long u64;

__device__ float g_h1[(size_t)MAXN * 64];
__device__ float g_agg1[(size_t)MAXN * 64];
__device__ float g_hd[(size_t)MAXN * 64];
__device__ float g_aggd[(size_t)MAXN * 64];
__device__ int   g_cnt[MAXN];
__device__ int   g_offs[MAXN];
__device__ int   g_cursor[MAXN];
__device__ int   g_ssrc[MAXE];
__device__ float g_dinv[MAXN];

__device__ __forceinline__ u64 pack2(float lo, float hi) {
    u64 r;
    asm("mov.b64 %0, {%1,%2};" : "=l"(r) : "f"(lo), "f"(hi));
    return r;
}
__device__ __forceinline__ void unpack2(u64 v, float& lo, float& hi) {
    asm("mov.b64 {%0,%1}, %2;" : "=f"(lo), "=f"(hi) : "l"(v));
}
__device__ __forceinline__ void fma2(u64& d, u64 a, u64 b) {
    asm("fma.rn.f32x2 %0, %1, %2, %0;" : "+l"(d) : "l"(a), "l"(b));
}

// ---------------------------------------------------------------------------
// Graph preprocessing
// ---------------------------------------------------------------------------
__global__ void count_kernel(const int* __restrict__ dst, int E) {
    int e = blockIdx.x * blockDim.x + threadIdx.x;
    if (e < E) atomicAdd(&g_cnt[dst[e]], 1);
}

__global__ void scan_kernel(int N) {
    __shared__ int sh[1024];
    int t = threadIdx.x;
    int per = (N + 1023) >> 10;
    int beg = t * per;
    int end = beg + per; if (end > N) end = N;
    int s = 0;
    for (int i = beg; i < end; i++) s += g_cnt[i];
    sh[t] = s;
    __syncthreads();
    for (int off = 1; off < 1024; off <<= 1) {
        int v = (t >= off) ? sh[t - off] : 0;
        __syncthreads();
        sh[t] += v;
        __syncthreads();
    }
    int run = (t > 0) ? sh[t - 1] : 0;
    for (int i = beg; i < end; i++) {
        g_offs[i] = run;
        g_cursor[i] = run;
        int c = g_cnt[i];
        run += c;
        g_dinv[i] = rsqrtf((float)(c + 1));  // +1 self loop
    }
}

__global__ void scatter_kernel(const int* __restrict__ src,
                               const int* __restrict__ dst, int E) {
    int e = blockIdx.x * blockDim.x + threadIdx.x;
    if (e < E) {
        int d = dst[e];
        int p = atomicAdd(&g_cursor[d], 1);
        g_ssrc[p] = src[e];
    }
}

// ---------------------------------------------------------------------------
// SGEMM (FFMA2): C[M,N] = A[M,K] @ B[K,N] (+ bias). BM=128, BN=64, BK=32,
// 256 threads, 8x4 microtile, accumulators packed in f32x2 pairs along M.
// As row stride = 130 floats (520B, 8B-aligned rows) so A pairs load as LDS.64.
// ---------------------------------------------------------------------------
__global__ __launch_bounds__(256, 2) void sgemm_kernel(
    const float* __restrict__ A, const float* __restrict__ B,
    float* __restrict__ C, const float* __restrict__ bias,
    int M, int N, int K) {
    const int BM = 128, BN = 64, BK = 32;
    __shared__ float As[BK][BM + 2];   // 130-float rows: 8-byte aligned
    __shared__ float Bs[BK][BN];
    int t = threadIdx.x;
    int tx = t & 15;       // col group: cols tx*4 .. tx*4+3
    int ty = t >> 4;       // row group: rows ty*8 .. ty*8+7
    int rowBase = blockIdx.y * BM;
    int colBase = blockIdx.x * BN;

    u64 acc[4][4];  // [row-pair][col]
#pragma unroll
    for (int i = 0; i < 4; i++)
#pragma unroll
        for (int j = 0; j < 4; j++) acc[i][j] = 0ull;

    for (int k0 = 0; k0 < K; k0 += BK) {
#pragma unroll
        for (int l = 0; l < 16; l++) {
            int idx = t + l * 256;
            int r = idx >> 5;
            int kk = idx & 31;
            int gr = rowBase + r;
            As[kk][r] = (gr < M) ? A[(size_t)gr * K + k0 + kk] : 0.f;
        }
#pragma unroll
        for (int l = 0; l < 8; l++) {
            int idx = t + l * 256;
            int kk = idx >> 6;
            int c = idx & 63;
            Bs[kk][c] = B[(size_t)(k0 + kk) * N + colBase + c];
        }
        __syncthreads();
#pragma unroll
        for (int k = 0; k < BK; k++) {
            u64 a2[4];
            const float* arow = &As[k][ty * 8];
#pragma unroll
            for (int i = 0; i < 4; i++)
                a2[i] = *(const u64*)(arow + 2 * i);   // packed (a[2i], a[2i+1])
            float4 bq = *(const float4*)&Bs[k][tx * 4];
            u64 b0 = pack2(bq.x, bq.x);
            u64 b1 = pack2(bq.y, bq.y);
            u64 b2 = pack2(bq.z, bq.z);
            u64 b3 = pack2(bq.w, bq.w);
#pragma unroll
            for (int i = 0; i < 4; i++) {
                fma2(acc[i][0], a2[i], b0);
                fma2(acc[i][1], a2[i], b1);
                fma2(acc[i][2], a2[i], b2);
                fma2(acc[i][3], a2[i], b3);
            }
        }
        __syncthreads();
    }

    float4 bv = make_float4(0.f, 0.f, 0.f, 0.f);
    if (bias) bv = *(const float4*)&bias[colBase + tx * 4];
#pragma unroll
    for (int i = 0; i < 4; i++) {
        float4 lo, hi;
        unpack2(acc[i][0], lo.x, hi.x);
        unpack2(acc[i][1], lo.y, hi.y);
        unpack2(acc[i][2], lo.z, hi.z);
        unpack2(acc[i][3], lo.w, hi.w);
        lo.x += bv.x; lo.y += bv.y; lo.z += bv.z; lo.w += bv.w;
        hi.x += bv.x; hi.y += bv.y; hi.z += bv.z; hi.w += bv.w;
        int r0 = rowBase + ty * 8 + 2 * i;
        if (r0 < M)
            *(float4*)&C[(size_t)r0 * N + colBase + tx * 4] = lo;
        if (r0 + 1 < M)
            *(float4*)&C[(size_t)(r0 + 1) * N + colBase + tx * 4] = hi;
    }
}

// ---------------------------------------------------------------------------
// Vectorized 64-wide aggregation: 16 lanes/node (float4 each), 16 nodes/block.
// ---------------------------------------------------------------------------
template <bool RELU, bool BIAS>
__global__ __launch_bounds__(256) void agg64v_kernel(
    const float* __restrict__ in, float* __restrict__ out,
    const float* __restrict__ bias, int N) {
    int node = blockIdx.x * 16 + (threadIdx.x >> 4);
    int q = threadIdx.x & 15;
    if (node >= N) return;
    const float4* F = (const float4*)in;
    int beg = g_offs[node];
    int cnt = g_cnt[node];
    float4 acc = make_float4(0.f, 0.f, 0.f, 0.f);
    int e = 0;
    for (; e + 4 <= cnt; e += 4) {
        int s0 = g_ssrc[beg + e + 0];
        int s1 = g_ssrc[beg + e + 1];
        int s2 = g_ssrc[beg + e + 2];
        int s3 = g_ssrc[beg + e + 3];
        float w0 = g_dinv[s0], w1 = g_dinv[s1], w2 = g_dinv[s2], w3 = g_dinv[s3];
        float4 v0 = F[(size_t)s0 * 16 + q];
        float4 v1 = F[(size_t)s1 * 16 + q];
        float4 v2 = F[(size_t)s2 * 16 + q];
        float4 v3 = F[(size_t)s3 * 16 + q];
        acc.x = fmaf(w0, v0.x, acc.x); acc.y = fmaf(w0, v0.y, acc.y);
        acc.z = fmaf(w0, v0.z, acc.z); acc.w = fmaf(w0, v0.w, acc.w);
        acc.x = fmaf(w1, v1.x, acc.x); acc.y = fmaf(w1, v1.y, acc.y);
        acc.z = fmaf(w1, v1.z, acc.z); acc.w = fmaf(w1, v1.w, acc.w);
        acc.x = fmaf(w2, v2.x, acc.x); acc.y = fmaf(w2, v2.y, acc.y);
        acc.z = fmaf(w2, v2.z, acc.z); acc.w = fmaf(w2, v2.w, acc.w);
        acc.x = fmaf(w3, v3.x, acc.x); acc.y = fmaf(w3, v3.y, acc.y);
        acc.z = fmaf(w3, v3.z, acc.z); acc.w = fmaf(w3, v3.w, acc.w);
    }
    for (; e < cnt; e++) {
        int s = g_ssrc[beg + e];
        float w = g_dinv[s];
        float4 v = F[(size_t)s * 16 + q];
        acc.x = fmaf(w, v.x, acc.x); acc.y = fmaf(w, v.y, acc.y);
        acc.z = fmaf(w, v.z, acc.z); acc.w = fmaf(w, v.w, acc.w);
    }
    float dn = g_dinv[node];
    float4 sv = F[(size_t)node * 16 + q];
    float4 o;
    o.x = dn * fmaf(dn, sv.x, acc.x);
    o.y = dn * fmaf(dn, sv.y, acc.y);
    o.z = dn * fmaf(dn, sv.z, acc.z);
    o.w = dn * fmaf(dn, sv.w, acc.w);
    if (BIAS) {
        float4 b = ((const float4*)bias)[q];
        o.x += b.x; o.y += b.y; o.z += b.z; o.w += b.w;
    }
    if (RELU) {
        o.x = fmaxf(o.x, 0.f); o.y = fmaxf(o.y, 0.f);
        o.z = fmaxf(o.z, 0.f); o.w = fmaxf(o.w, 0.f);
    }
    ((float4*)out)[(size_t)node * 16 + q] = o;
}

// ---------------------------------------------------------------------------
// Fused latent chain: z = agg1 @ Wz + bz ; pred = z @ Wp + bp ;
// hd = relu(z @ Wd + bd). 8 rows per block (1 warp per row).
// ---------------------------------------------------------------------------
__global__ __launch_bounds__(256) void latent_kernel(
    const float* __restrict__ Wz, const float* __restrict__ bz,
    const float* __restrict__ Wd, const float* __restrict__ bd,
    const float* __restrict__ Wp, const float* __restrict__ bp,
    float* __restrict__ zout, float* __restrict__ pout, int N) {
    __shared__ float sWz[64 * 32];
    __shared__ float sWd[32 * 64];
    __shared__ float sWp[32 * 3];
    __shared__ float sz[8][33];
    int t = threadIdx.x;
    for (int i = t; i < 64 * 32; i += 256) sWz[i] = Wz[i];
    for (int i = t; i < 32 * 64; i += 256) sWd[i] = Wd[i];
    if (t < 96) sWp[t] = Wp[t];
    __syncthreads();

    int r = t >> 5;
    int lane = t & 31;
    int row = blockIdx.x * 8 + r;

    float zv = 0.f;
    if (row < N) {
        zv = bz[lane];
        const float* hrow = &g_agg1[(size_t)row * 64];
#pragma unroll
        for (int k = 0; k < 64; k++) zv = fmaf(hrow[k], sWz[k * 32 + lane], zv);
        zout[(size_t)row * 32 + lane] = zv;
    }
    sz[r][lane] = zv;

    float p0 = zv * sWp[lane * 3 + 0];
    float p1 = zv * sWp[lane * 3 + 1];
    float p2 = zv * sWp[lane * 3 + 2];
#pragma unroll
    for (int off = 16; off; off >>= 1) {
        p0 += __shfl_xor_sync(0xffffffffu, p0, off);
        p1 += __shfl_xor_sync(0xffffffffu, p1, off);
        p2 += __shfl_xor_sync(0xffffffffu, p2, off);
    }
    if (row < N && lane == 0) {
        pout[(size_t)row * 3 + 0] = p0 + bp[0];
        pout[(size_t)row * 3 + 1] = p1 + bp[1];
        pout[(size_t)row * 3 + 2] = p2 + bp[2];
    }
    __syncthreads();

    if (row < N) {
        float a0 = bd[lane], a1 = bd[lane + 32];
#pragma unroll
        for (int c = 0; c < 32; c++) {
            float zc = sz[r][c];
            a0 = fmaf(zc, sWd[c * 64 + lane], a0);
            a1 = fmaf(zc, sWd[c * 64 + lane + 32], a1);
        }
        g_hd[(size_t)row * 64 + lane] = fmaxf(a0, 0.f);
        g_hd[(size_t)row * 64 + lane + 32] = fmaxf(a1, 0.f);
    }
}

// ---------------------------------------------------------------------------
// Launch
// ---------------------------------------------------------------------------
extern "C" void kernel_launch(void* const* d_in, const int* in_sizes, int n_in,
                              void* d_out, int out_size) {
    const float* x         = (const float*)d_in[0];
    const int*   ei        = (const int*)d_in[1];
    const float* W_enc_gnn = (const float*)d_in[3];
    const float* b_enc_gnn = (const float*)d_in[4];
    const float* W_enc_fc  = (const float*)d_in[5];
    const float* b_enc_fc  = (const float*)d_in[6];
    const float* W_dec_fc  = (const float*)d_in[7];
    const float* b_dec_fc  = (const float*)d_in[8];
    const float* W_dec_gnn = (const float*)d_in[9];
    const float* b_dec_gnn = (const float*)d_in[10];
    const float* W_cond    = (const float*)d_in[11];
    const float* b_cond    = (const float*)d_in[12];

    int N = in_sizes[0] / 256;
    int E = in_sizes[1] / 2;
    const int* src = ei;
    const int* dst = ei + E;

    float* out  = (float*)d_out;
    float* xr   = out;                        // [N,256]
    float* zout = out + (size_t)N * 256;      // [N,32]
    float* pout = out + (size_t)N * 288;      // [N,3]

    float *p_h1, *p_agg1, *p_hd, *p_aggd;
    int* p_cnt;
    cudaGetSymbolAddress((void**)&p_h1, g_h1);
    cudaGetSymbolAddress((void**)&p_agg1, g_agg1);
    cudaGetSymbolAddress((void**)&p_hd, g_hd);
    cudaGetSymbolAddress((void**)&p_aggd, g_aggd);
    cudaGetSymbolAddress((void**)&p_cnt, g_cnt);

    // 1. graph prep (CSR by dst + dinv)
    cudaMemsetAsync(p_cnt, 0, (size_t)N * sizeof(int));
    count_kernel<<<(E + 255) / 256, 256>>>(dst, E);
    scan_kernel<<<1, 1024>>>(N);
    scatter_kernel<<<(E + 255) / 256, 256>>>(src, dst, E);

    // 2. encoder GCN: h1 = x @ W_enc_gnn ; agg1 = relu(agg(h1) + b)
    sgemm_kernel<<<dim3(1, (N + 127) / 128), 256>>>(x, W_enc_gnn, p_h1, nullptr,
                                                    N, 64, 256);
    agg64v_kernel<true, true><<<(N + 15) / 16, 256>>>(p_h1, p_agg1, b_enc_gnn, N);

    // 3. latent chain: z, pred, hd
    latent_kernel<<<(N + 7) / 8, 256>>>(W_enc_fc, b_enc_fc, W_dec_fc, b_dec_fc,
                                        W_cond, b_cond, zout, pout, N);

    // 4. decoder GCN reordered: aggd = agg(hd) ; x_recon = aggd @ W + b
    agg64v_kernel<false, false><<<(N + 15) / 16, 256>>>(p_hd, p_aggd, nullptr, N);
    sgemm_kernel<<<dim3(4, (N + 127) / 128), 256>>>(p_aggd, W_dec_gnn, xr,
                                                    b_dec_gnn, N, 256, 64);
}

// round 7
// speedup vs baseline: 1.5121x; 1.0874x over previous
#include <cuda_runtime.h>
#include <cuda_bf16.h>
#include <math.h>

// ---------------------------------------------------------------------------
// GNN-VAE. Dims: N=50000, E=800000, F: 256 -> 64 -> 32 -> 64 -> 256, pred 3.
// Output layout: [x_recon (N*256) | z (N*32) | pred (N*3)]
// Decoder reordered via GCN linearity: all edge gathers in 64-dim space.
// GEMMs on tensor cores: mma.sync.m16n8k8 tf32 with 3xTF32 split (fp32-grade
// accuracy: A,B split into big+small tf32; big*big + big*small + small*big).
// ---------------------------------------------------------------------------

#define MAXN 50048
#define MAXE 800000

__device__ float g_h1[(size_t)MAXN * 64];
__device__ float g_agg1[(size_t)MAXN * 64];
__device__ float g_hd[(size_t)MAXN * 64];
__device__ float g_aggd[(size_t)MAXN * 64];
__device__ int   g_cnt[MAXN];
__device__ int   g_offs[MAXN];
__device__ int   g_cursor[MAXN];
__device__ int   g_ssrc[MAXE];
__device__ float g_dinv[MAXN];

// ---------------------------------------------------------------------------
// Graph preprocessing
// ---------------------------------------------------------------------------
__global__ void count_kernel(const int* __restrict__ dst, int E) {
    int e = blockIdx.x * blockDim.x + threadIdx.x;
    if (e < E) atomicAdd(&g_cnt[dst[e]], 1);
}

__global__ void scan_kernel(int N) {
    __shared__ int sh[1024];
    int t = threadIdx.x;
    int per = (N + 1023) >> 10;
    int beg = t * per;
    int end = beg + per; if (end > N) end = N;
    int s = 0;
    for (int i = beg; i < end; i++) s += g_cnt[i];
    sh[t] = s;
    __syncthreads();
    for (int off = 1; off < 1024; off <<= 1) {
        int v = (t >= off) ? sh[t - off] : 0;
        __syncthreads();
        sh[t] += v;
        __syncthreads();
    }
    int run = (t > 0) ? sh[t - 1] : 0;
    for (int i = beg; i < end; i++) {
        g_offs[i] = run;
        g_cursor[i] = run;
        int c = g_cnt[i];
        run += c;
        g_dinv[i] = rsqrtf((float)(c + 1));  // +1 self loop
    }
}

__global__ void scatter_kernel(const int* __restrict__ src,
                               const int* __restrict__ dst, int E) {
    int e = blockIdx.x * blockDim.x + threadIdx.x;
    if (e < E) {
        int d = dst[e];
        int p = atomicAdd(&g_cursor[d], 1);
        g_ssrc[p] = src[e];
    }
}

// ---------------------------------------------------------------------------
// TF32 helpers
// ---------------------------------------------------------------------------
__device__ __forceinline__ unsigned f2tf32(float f) {
    unsigned u;
    asm("cvt.rna.tf32.f32 %0, %1;" : "=r"(u) : "f"(f));
    return u;
}
__device__ __forceinline__ void split_tf32(float f, unsigned& big, unsigned& sml) {
    big = f2tf32(f);
    float res = f - __uint_as_float(big);
    sml = f2tf32(res);
}

#define MMA_TF32(D, A0, A1, A2, A3, B0, B1)                                   \
    asm volatile(                                                             \
        "mma.sync.aligned.m16n8k8.row.col.f32.tf32.tf32.f32 "                 \
        "{%0,%1,%2,%3}, {%4,%5,%6,%7}, {%8,%9}, {%0,%1,%2,%3};\n"             \
        : "+f"((D)[0]), "+f"((D)[1]), "+f"((D)[2]), "+f"((D)[3])              \
        : "r"(A0), "r"(A1), "r"(A2), "r"(A3), "r"(B0), "r"(B1))

// ---------------------------------------------------------------------------
// Tensor-core GEMM: C[M,N] = A[M,K] @ B[K,N] (+ bias).
// BM=128, BN=64, BK=32, 256 threads = 8 warps in 4(M)x2(N) layout;
// each warp: 32x32 = 2 mtiles x 4 ntiles of m16n8. 3xTF32 accuracy.
// As[m][k] stride 36: frag LDS bank = (4q+r) -> conflict-free.
// Bs[n][k] stride 36: same property.
// ---------------------------------------------------------------------------
__global__ __launch_bounds__(256) void tgemm_kernel(
    const float* __restrict__ A, const float* __restrict__ B,
    float* __restrict__ C, const float* __restrict__ bias,
    int M, int N, int K) {
    __shared__ float As[128][36];
    __shared__ float Bs[64][36];
    int t = threadIdx.x;
    int lane = t & 31;
    int wid = t >> 5;
    int wm = wid & 3;        // M quarter (32 rows)
    int wn = wid >> 2;       // N half (32 cols)
    int q = lane >> 2;       // 0..7
    int r = lane & 3;        // 0..3
    int rowBase = blockIdx.y * 128;
    int colBase = blockIdx.x * 64;

    float acc[2][4][4];
#pragma unroll
    for (int mt = 0; mt < 2; mt++)
#pragma unroll
        for (int nt = 0; nt < 4; nt++)
#pragma unroll
            for (int i = 0; i < 4; i++) acc[mt][nt][i] = 0.f;

    int arow = t >> 3;           // 0..31 (m row group)
    int ac4 = (t & 7) * 4;       // k chunk 0,4,..28
    int bn = t >> 2;             // 0..63 (n)
    int ba8 = (t & 3) * 8;       // k chunk 0,8,16,24

    for (int k0 = 0; k0 < K; k0 += 32) {
        // A tile -> As[m][k] (float4 per store, conflict-free)
#pragma unroll
        for (int j = 0; j < 4; j++) {
            int m = arow + 32 * j;
            int gr = rowBase + m;
            float4 v = make_float4(0.f, 0.f, 0.f, 0.f);
            if (gr < M) v = *(const float4*)&A[(size_t)gr * K + k0 + ac4];
            *(float4*)&As[m][ac4] = v;
        }
        // B tile -> Bs[n][k] (transpose in smem)
#pragma unroll
        for (int j = 0; j < 8; j++) {
            Bs[bn][ba8 + j] = B[(size_t)(k0 + ba8 + j) * N + colBase + bn];
        }
        __syncthreads();
#pragma unroll
        for (int ks = 0; ks < 4; ks++) {
            int kb = ks * 8;
            unsigned ab[2][4], as[2][4];
#pragma unroll
            for (int mt = 0; mt < 2; mt++) {
                int m0 = wm * 32 + mt * 16;
                float f0 = As[m0 + q][kb + r];
                float f1 = As[m0 + q + 8][kb + r];
                float f2 = As[m0 + q][kb + r + 4];
                float f3 = As[m0 + q + 8][kb + r + 4];
                split_tf32(f0, ab[mt][0], as[mt][0]);
                split_tf32(f1, ab[mt][1], as[mt][1]);
                split_tf32(f2, ab[mt][2], as[mt][2]);
                split_tf32(f3, ab[mt][3], as[mt][3]);
            }
#pragma unroll
            for (int nt = 0; nt < 4; nt++) {
                int n0 = wn * 32 + nt * 8;
                float g0 = Bs[n0 + q][kb + r];
                float g1 = Bs[n0 + q][kb + r + 4];
                unsigned bb0, bs0, bb1, bs1;
                split_tf32(g0, bb0, bs0);
                split_tf32(g1, bb1, bs1);
#pragma unroll
                for (int mt = 0; mt < 2; mt++) {
                    MMA_TF32(acc[mt][nt], ab[mt][0], ab[mt][1], ab[mt][2],
                             ab[mt][3], bb0, bb1);
                    MMA_TF32(acc[mt][nt], ab[mt][0], ab[mt][1], ab[mt][2],
                             ab[mt][3], bs0, bs1);
                    MMA_TF32(acc[mt][nt], as[mt][0], as[mt][1], as[mt][2],
                             as[mt][3], bb0, bb1);
                }
            }
        }
        __syncthreads();
    }

    // Epilogue: c0/c1 -> (row, 2r), (row, 2r+1); c2/c3 -> row+8
#pragma unroll
    for (int mt = 0; mt < 2; mt++) {
#pragma unroll
        for (int nt = 0; nt < 4; nt++) {
            int col = colBase + wn * 32 + nt * 8 + 2 * r;
            float2 bv = make_float2(0.f, 0.f);
            if (bias) bv = *(const float2*)&bias[col];
            int row0 = rowBase + wm * 32 + mt * 16 + q;
            if (row0 < M) {
                float2 o = make_float2(acc[mt][nt][0] + bv.x,
                                       acc[mt][nt][1] + bv.y);
                *(float2*)&C[(size_t)row0 * N + col] = o;
            }
            int row1 = row0 + 8;
            if (row1 < M) {
                float2 o = make_float2(acc[mt][nt][2] + bv.x,
                                       acc[mt][nt][3] + bv.y);
                *(float2*)&C[(size_t)row1 * N + col] = o;
            }
        }
    }
}

// ---------------------------------------------------------------------------
// Vectorized 64-wide aggregation: 16 lanes/node (float4 each), 16 nodes/block.
// ---------------------------------------------------------------------------
template <bool RELU, bool BIAS>
__global__ __launch_bounds__(256) void agg64v_kernel(
    const float* __restrict__ in, float* __restrict__ out,
    const float* __restrict__ bias, int N) {
    int node = blockIdx.x * 16 + (threadIdx.x >> 4);
    int q = threadIdx.x & 15;
    if (node >= N) return;
    const float4* F = (const float4*)in;
    int beg = g_offs[node];
    int cnt = g_cnt[node];
    float4 acc = make_float4(0.f, 0.f, 0.f, 0.f);
    int e = 0;
    for (; e + 4 <= cnt; e += 4) {
        int s0 = g_ssrc[beg + e + 0];
        int s1 = g_ssrc[beg + e + 1];
        int s2 = g_ssrc[beg + e + 2];
        int s3 = g_ssrc[beg + e + 3];
        float w0 = g_dinv[s0], w1 = g_dinv[s1], w2 = g_dinv[s2], w3 = g_dinv[s3];
        float4 v0 = F[(size_t)s0 * 16 + q];
        float4 v1 = F[(size_t)s1 * 16 + q];
        float4 v2 = F[(size_t)s2 * 16 + q];
        float4 v3 = F[(size_t)s3 * 16 + q];
        acc.x = fmaf(w0, v0.x, acc.x); acc.y = fmaf(w0, v0.y, acc.y);
        acc.z = fmaf(w0, v0.z, acc.z); acc.w = fmaf(w0, v0.w, acc.w);
        acc.x = fmaf(w1, v1.x, acc.x); acc.y = fmaf(w1, v1.y, acc.y);
        acc.z = fmaf(w1, v1.z, acc.z); acc.w = fmaf(w1, v1.w, acc.w);
        acc.x = fmaf(w2, v2.x, acc.x); acc.y = fmaf(w2, v2.y, acc.y);
        acc.z = fmaf(w2, v2.z, acc.z); acc.w = fmaf(w2, v2.w, acc.w);
        acc.x = fmaf(w3, v3.x, acc.x); acc.y = fmaf(w3, v3.y, acc.y);
        acc.z = fmaf(w3, v3.z, acc.z); acc.w = fmaf(w3, v3.w, acc.w);
    }
    for (; e < cnt; e++) {
        int s = g_ssrc[beg + e];
        float w = g_dinv[s];
        float4 v = F[(size_t)s * 16 + q];
        acc.x = fmaf(w, v.x, acc.x); acc.y = fmaf(w, v.y, acc.y);
        acc.z = fmaf(w, v.z, acc.z); acc.w = fmaf(w, v.w, acc.w);
    }
    float dn = g_dinv[node];
    float4 sv = F[(size_t)node * 16 + q];
    float4 o;
    o.x = dn * fmaf(dn, sv.x, acc.x);
    o.y = dn * fmaf(dn, sv.y, acc.y);
    o.z = dn * fmaf(dn, sv.z, acc.z);
    o.w = dn * fmaf(dn, sv.w, acc.w);
    if (BIAS) {
        float4 b = ((const float4*)bias)[q];
        o.x += b.x; o.y += b.y; o.z += b.z; o.w += b.w;
    }
    if (RELU) {
        o.x = fmaxf(o.x, 0.f); o.y = fmaxf(o.y, 0.f);
        o.z = fmaxf(o.z, 0.f); o.w = fmaxf(o.w, 0.f);
    }
    ((float4*)out)[(size_t)node * 16 + q] = o;
}

// ---------------------------------------------------------------------------
// Fused latent chain: z = agg1 @ Wz + bz ; pred = z @ Wp + bp ;
// hd = relu(z @ Wd + bd). 8 rows per block (1 warp per row).
// ---------------------------------------------------------------------------
__global__ __launch_bounds__(256) void latent_kernel(
    const float* __restrict__ Wz, const float* __restrict__ bz,
    const float* __restrict__ Wd, const float* __restrict__ bd,
    const float* __restrict__ Wp, const float* __restrict__ bp,
    float* __restrict__ zout, float* __restrict__ pout, int N) {
    __shared__ float sWz[64 * 32];
    __shared__ float sWd[32 * 64];
    __shared__ float sWp[32 * 3];
    __shared__ float sz[8][33];
    int t = threadIdx.x;
    for (int i = t; i < 64 * 32; i += 256) sWz[i] = Wz[i];
    for (int i = t; i < 32 * 64; i += 256) sWd[i] = Wd[i];
    if (t < 96) sWp[t] = Wp[t];
    __syncthreads();

    int r = t >> 5;
    int lane = t & 31;
    int row = blockIdx.x * 8 + r;

    float zv = 0.f;
    if (row < N) {
        zv = bz[lane];
        const float* hrow = &g_agg1[(size_t)row * 64];
#pragma unroll
        for (int k = 0; k < 64; k++) zv = fmaf(hrow[k], sWz[k * 32 + lane], zv);
        zout[(size_t)row * 32 + lane] = zv;
    }
    sz[r][lane] = zv;

    float p0 = zv * sWp[lane * 3 + 0];
    float p1 = zv * sWp[lane * 3 + 1];
    float p2 = zv * sWp[lane * 3 + 2];
#pragma unroll
    for (int off = 16; off; off >>= 1) {
        p0 += __shfl_xor_sync(0xffffffffu, p0, off);
        p1 += __shfl_xor_sync(0xffffffffu, p1, off);
        p2 += __shfl_xor_sync(0xffffffffu, p2, off);
    }
    if (row < N && lane == 0) {
        pout[(size_t)row * 3 + 0] = p0 + bp[0];
        pout[(size_t)row * 3 + 1] = p1 + bp[1];
        pout[(size_t)row * 3 + 2] = p2 + bp[2];
    }
    __syncthreads();

    if (row < N) {
        float a0 = bd[lane], a1 = bd[lane + 32];
#pragma unroll
        for (int c = 0; c < 32; c++) {
            float zc = sz[r][c];
            a0 = fmaf(zc, sWd[c * 64 + lane], a0);
            a1 = fmaf(zc, sWd[c * 64 + lane + 32], a1);
        }
        g_hd[(size_t)row * 64 + lane] = fmaxf(a0, 0.f);
        g_hd[(size_t)row * 64 + lane + 32] = fmaxf(a1, 0.f);
    }
}

// ---------------------------------------------------------------------------
// Launch
// ---------------------------------------------------------------------------
extern "C" void kernel_launch(void* const* d_in, const int* in_sizes, int n_in,
                              void* d_out, int out_size) {
    const float* x         = (const float*)d_in[0];
    const int*   ei        = (const int*)d_in[1];
    const float* W_enc_gnn = (const float*)d_in[3];
    const float* b_enc_gnn = (const float*)d_in[4];
    const float* W_enc_fc  = (const float*)d_in[5];
    const float* b_enc_fc  = (const float*)d_in[6];
    const float* W_dec_fc  = (const float*)d_in[7];
    const float* b_dec_fc  = (const float*)d_in[8];
    const float* W_dec_gnn = (const float*)d_in[9];
    const float* b_dec_gnn = (const float*)d_in[10];
    const float* W_cond    = (const float*)d_in[11];
    const float* b_cond    = (const float*)d_in[12];

    int N = in_sizes[0] / 256;
    int E = in_sizes[1] / 2;
    const int* src = ei;
    const int* dst = ei + E;

    float* out  = (float*)d_out;
    float* xr   = out;                        // [N,256]
    float* zout = out + (size_t)N * 256;      // [N,32]
    float* pout = out + (size_t)N * 288;      // [N,3]

    float *p_h1, *p_agg1, *p_hd, *p_aggd;
    int* p_cnt;
    cudaGetSymbolAddress((void**)&p_h1, g_h1);
    cudaGetSymbolAddress((void**)&p_agg1, g_agg1);
    cudaGetSymbolAddress((void**)&p_hd, g_hd);
    cudaGetSymbolAddress((void**)&p_aggd, g_aggd);
    cudaGetSymbolAddress((void**)&p_cnt, g_cnt);

    // 1. graph prep (CSR by dst + dinv)
    cudaMemsetAsync(p_cnt, 0, (size_t)N * sizeof(int));
    count_kernel<<<(E + 255) / 256, 256>>>(dst, E);
    scan_kernel<<<1, 1024>>>(N);
    scatter_kernel<<<(E + 255) / 256, 256>>>(src, dst, E);

    // 2. encoder GCN: h1 = x @ W_enc_gnn ; agg1 = relu(agg(h1) + b)
    tgemm_kernel<<<dim3(1, (N + 127) / 128), 256>>>(x, W_enc_gnn, p_h1, nullptr,
                                                    N, 64, 256);
    agg64v_kernel<true, true><<<(N + 15) / 16, 256>>>(p_h1, p_agg1, b_enc_gnn, N);

    // 3. latent chain: z, pred, hd
    latent_kernel<<<(N + 7) / 8, 256>>>(W_enc_fc, b_enc_fc, W_dec_fc, b_dec_fc,
                                        W_cond, b_cond, zout, pout, N);

    // 4. decoder GCN reordered: aggd = agg(hd) ; x_recon = aggd @ W + b
    agg64v_kernel<false, false><<<(N + 15) / 16, 256>>>(p_hd, p_aggd, nullptr, N);
    tgemm_kernel<<<dim3(4, (N + 127) / 128), 256>>>(p_aggd, W_dec_gnn, xr,
                                                    b_dec_gnn, N, 256, 64);
}